// round 15
// baseline (speedup 1.0000x reference)
#include <cuda_runtime.h>
#include <cuda_fp16.h>
#include <stdint.h>

#define D  128
#define NT 256

// SMEM float offsets
#define XS 0            // x tile [64][128] tf32-rounded, swizzled (32KB)
#define HS 8192         // h tile [64][128] tf32-rounded; later r*h  (32KB)
#define PB 16384        // 3 x quarter-panel buffers (3 x 16KB)
#define SMEM_BYTES ((16384 + 3 * 4096) * 4)   // 114,688 B -> 2 CTAs/SM

// ---------------------------------------------------------------------------
// device globals: biases + prepped weight panel images
// ---------------------------------------------------------------------------
__device__ float g_bias[3 * D];
__device__ __align__(256) float g_wp[20 * 4096];  // imgs: Wz q0-3, Uz, Wr+Ur, Wh, Uh

__device__ __forceinline__ float f2tf(float f) {      // round fp32 -> tf32 grid
    uint32_t u;
    asm("cvt.rna.tf32.f32 %0, %1;" : "=r"(u) : "f"(f));
    return __uint_as_float(u);
}
__device__ __forceinline__ float sigmoidf_(float v) { return 1.0f / (1.0f + expf(-v)); }

__device__ __forceinline__ uint32_t smem_u32(const void* p) {
    uint32_t a;
    asm("{ .reg .u64 t; cvta.to.shared.u64 t, %1; cvt.u32.u64 %0, t; }" : "=r"(a) : "l"(p));
    return a;
}
__device__ __forceinline__ void cp16(uint32_t saddr, const void* gaddr) {
    asm volatile("cp.async.cg.shared.global [%0], [%1], 16;" :: "r"(saddr), "l"(gaddr));
}
#define CP_COMMIT() asm volatile("cp.async.commit_group;" ::: "memory")
#define CP_WAIT1()  asm volatile("cp.async.wait_group 1;" ::: "memory")
#define CP_WAIT0()  asm volatile("cp.async.wait_group 0;" ::: "memory")

// ---------------------------------------------------------------------------
// prep: bake weights into SMEM-image layout (blocks 0..159) + bias sums (160..162)
// panel p = G*4 + q; element B_G(n,k), k=q*32+k', at p*4096 + n*32 + (k'^((n&7)<<2))
// G0..2 transposed (x@W), G3..4 natural (x@W^T)
// ---------------------------------------------------------------------------
__global__ void prep_kernel(const float* __restrict__ Wz, const float* __restrict__ Uz,
                            const float* __restrict__ Wr, const float* __restrict__ Ur,
                            const float* __restrict__ Wh, const float* __restrict__ Uh,
                            const float* __restrict__ Bz, const float* __restrict__ Br,
                            const float* __restrict__ Bh) {
    if (blockIdx.x >= 320) {                 // bias: one block per matrix
        int m = blockIdx.x - 320;
        int j = threadIdx.x;
        if (j < D) {
            const float* B = (m == 0) ? Bz : (m == 1) ? Br : Bh;
            float s = 0.f;
            for (int i = 0; i < D; ++i) s += B[i * D + j];   // coalesced
            g_bias[m * D + j] = s;
        }
        return;
    }
    int idx = blockIdx.x * blockDim.x + threadIdx.x;   // 81920 weight elements
    int G   = idx >> 14;
    int rem = idx & 16383;
    int q   = rem >> 12;
    int r2  = rem & 4095;
    int n   = r2 >> 5;
    int kx  = r2 & 31;
    int k   = q * 32 + (kx ^ ((n & 7) << 2));
    float v;
    if      (G == 0) v = Wz[k * D + n];
    else if (G == 1) v = Uz[k * D + n];
    else if (G == 2) v = Wr[k * D + n] + Ur[k * D + n];
    else if (G == 3) v = Wh[n * D + k];
    else             v = Uh[n * D + k];
    g_wp[idx] = f2tf(v);
}

// ---------------------------------------------------------------------------
// mma helpers
// ---------------------------------------------------------------------------
__device__ __forceinline__ void mma8(float* d, const uint32_t* a, uint32_t b0, uint32_t b1) {
    asm volatile(
        "mma.sync.aligned.m16n8k8.row.col.f32.tf32.tf32.f32 "
        "{%0,%1,%2,%3}, {%4,%5,%6,%7}, {%8,%9}, {%0,%1,%2,%3};"
        : "+f"(d[0]), "+f"(d[1]), "+f"(d[2]), "+f"(d[3])
        : "r"(a[0]), "r"(a[1]), "r"(a[2]), "r"(a[3]), "r"(b0), "r"(b1));
}

// one quarter-K slab: warp tile 32M x 32N x 32K (2 msub x 4 nsub)
// tile index (ms,ns) -> acc[ms*4+ns]
__device__ __forceinline__ void mma_q(const float* __restrict__ As, int koff,
                                      const float* __restrict__ Ws,
                                      float acc[8][4],
                                      int mrow0, int ncol0, int g, int t) {
    const float* a0 = As + (mrow0 + g) * D + koff;
    const float* a1 = a0 + 8 * D;
    const float* a2 = a0 + 16 * D;
    const float* a3 = a0 + 24 * D;
#pragma unroll
    for (int kk = 0; kk < 4; ++kk) {
        const int off1 = (kk * 8 + t) ^ (g << 2);
        const int off2 = off1 ^ 4;
        uint32_t A0[4], A1[4];
        A0[0] = __float_as_uint(a0[off1]); A0[1] = __float_as_uint(a1[off1]);
        A0[2] = __float_as_uint(a0[off2]); A0[3] = __float_as_uint(a1[off2]);
        A1[0] = __float_as_uint(a2[off1]); A1[1] = __float_as_uint(a3[off1]);
        A1[2] = __float_as_uint(a2[off2]); A1[3] = __float_as_uint(a3[off2]);
#pragma unroll
        for (int ns = 0; ns < 4; ++ns) {
            const float* bp = Ws + (ncol0 + ns * 8 + g) * 32;
            uint32_t b0 = __float_as_uint(bp[off1]);
            uint32_t b1 = __float_as_uint(bp[off2]);
            mma8(acc[ns],     A0, b0, b1);
            mma8(acc[4 + ns], A1, b0, b1);
        }
    }
}

// ---------------------------------------------------------------------------
// fused GRU: 64 rows/CTA, 256 threads (8 warps of 32x32), 2 CTAs/SM
// single live accumulator; z parked as fp16x2 in registers
// ---------------------------------------------------------------------------
__global__ __launch_bounds__(NT, 2)
void gru_kernel(const float* __restrict__ x, const float* __restrict__ h,
                float* __restrict__ out, long long half_off) {
    extern __shared__ float sm[];
    const int tid   = threadIdx.x;
    const int lane  = tid & 31;
    const int warp  = tid >> 5;
    const int g     = lane >> 2;
    const int t     = lane & 3;
    const int mrow0 = (warp >> 2) * 32;    // 0, 32
    const int ncol0 = (warp & 3) * 32;     // 0,32,64,96
    const long long row0 = (long long)blockIdx.x * 64;

    const uint32_t pb = smem_u32(sm + PB) + (uint32_t)tid * 16;

    // ---- kick off panel pipeline: img0 -> buf0, img1 -> buf1 ----
    {
        const char* s0 = (const char*)g_wp + tid * 16;
#pragma unroll
        for (int j = 0; j < 4; ++j) cp16(pb + j * 4096, s0 + j * 4096);
        CP_COMMIT();
        const char* s1 = (const char*)(g_wp + 4096) + tid * 16;
#pragma unroll
        for (int j = 0; j < 4; ++j) cp16(pb + 16384 + j * 4096, s1 + j * 4096);
        CP_COMMIT();
    }

    // ---- stage x, h (tf32-rounded) into swizzled tiles (overlaps cp.async) ----
#pragma unroll
    for (int i = 0; i < 8; ++i) {
        int idx = tid + i * NT;
        int r = idx >> 5, c = (idx & 31) << 2;
        int sw = r * D + (c ^ ((r & 7) << 2));
        float4 vx = *(const float4*)(x + (row0 + r) * D + c);
        *(float4*)(sm + XS + sw) = make_float4(f2tf(vx.x), f2tf(vx.y), f2tf(vx.z), f2tf(vx.w));
        float4 vh = *(const float4*)(h + (row0 + r) * D + c);
        *(float4*)(sm + HS + sw) = make_float4(f2tf(vh.x), f2tf(vh.y), f2tf(vh.z), f2tf(vh.w));
    }
    CP_WAIT1();
    __syncthreads();

    float acc[8][4];
#pragma unroll
    for (int q = 0; q < 8; ++q)
#pragma unroll
        for (int j = 0; j < 4; ++j) acc[q][j] = 0.f;

    // slab p: issue img p+2 -> buf (p+2)%3; mma img p; wait img p+1; sync
#define QITER(p, ABASE) do {                                                   \
        if ((p) + 2 <= 19) {                                                   \
            uint32_t dst = pb + (uint32_t)((((p) + 2) % 3) * 16384);           \
            const char* s_ = (const char*)(g_wp + ((p) + 2) * 4096) + tid * 16;\
            _Pragma("unroll")                                                  \
            for (int j_ = 0; j_ < 4; ++j_) cp16(dst + j_ * 4096, s_ + j_ * 4096); \
            CP_COMMIT();                                                       \
        }                                                                      \
        mma_q(sm + (ABASE), ((p) & 3) * 32, sm + PB + (((p) % 3) * 4096),      \
              acc, mrow0, ncol0, g, t);                                        \
        if ((p) + 2 <= 19) { CP_WAIT1(); } else { CP_WAIT0(); }                \
        __syncthreads();                                                       \
    } while (0)

    // ---- phase 1: z_pre = x@Wz + h@Uz (imgs 0-7) ----
    QITER(0, XS); QITER(1, XS); QITER(2, XS); QITER(3, XS);
    QITER(4, HS); QITER(5, HS); QITER(6, HS); QITER(7, HS);

    // E1a: z = sigmoid(z_pre + bz) -> packed fp16x2 registers; reset acc
    uint32_t zpk[16];
#pragma unroll
    for (int q = 0; q < 8; ++q) {
        int ns = q & 3;
        int c0 = ncol0 + ns * 8 + 2 * t;
        float bz0 = __ldg(&g_bias[c0]), bz1 = __ldg(&g_bias[c0 + 1]);
        float z0 = sigmoidf_(acc[q][0] + bz0);
        float z1 = sigmoidf_(acc[q][1] + bz1);
        float z2 = sigmoidf_(acc[q][2] + bz0);
        float z3 = sigmoidf_(acc[q][3] + bz1);
        __half2 p01 = __floats2half2_rn(z0, z1);
        __half2 p23 = __floats2half2_rn(z2, z3);
        zpk[q * 2]     = *(uint32_t*)&p01;
        zpk[q * 2 + 1] = *(uint32_t*)&p23;
        acc[q][0] = 0.f; acc[q][1] = 0.f; acc[q][2] = 0.f; acc[q][3] = 0.f;
    }

    // ---- phase 2: r_pre = x@(Wr+Ur) (imgs 8-11) ----
    QITER(8, XS); QITER(9, XS); QITER(10, XS); QITER(11, XS);

    // E1b: r = sigmoid(r_pre + br); HS <- f2tf(r * h); reset acc
#pragma unroll
    for (int q = 0; q < 8; ++q) {
        int ns = q & 3, ms = q >> 2;
        int c0 = ncol0 + ns * 8 + 2 * t;
        float br0 = __ldg(&g_bias[D + c0]), br1 = __ldg(&g_bias[D + c0 + 1]);
        int r1 = mrow0 + ms * 16 + g;
        int swc = c0 ^ (g << 2);
        float2 hA = *(float2*)(sm + HS + r1 * D + swc);
        float2 hB = *(float2*)(sm + HS + (r1 + 8) * D + swc);
        float q0 = sigmoidf_(acc[q][0] + br0);
        float q1 = sigmoidf_(acc[q][1] + br1);
        float q2 = sigmoidf_(acc[q][2] + br0);
        float q3 = sigmoidf_(acc[q][3] + br1);
        *(float2*)(sm + HS + r1 * D + swc)       = make_float2(f2tf(q0 * hA.x), f2tf(q1 * hA.y));
        *(float2*)(sm + HS + (r1 + 8) * D + swc) = make_float2(f2tf(q2 * hB.x), f2tf(q3 * hB.y));
        acc[q][0] = 0.f; acc[q][1] = 0.f; acc[q][2] = 0.f; acc[q][3] = 0.f;
    }
    // slabs 12-15 read XS only; per-slab syncs separate E1b's HS writes from slab 16

    // ---- phase 3: hc_pre = x@Wh^T + rh@Uh^T (imgs 12-19) ----
    QITER(12, XS); QITER(13, XS); QITER(14, XS); QITER(15, XS);
    QITER(16, HS); QITER(17, HS); QITER(18, HS); QITER(19, HS);
#undef QITER

    // ---- E2: h_cand = tanh(hc_pre+bh); h_t = (1-z)*h_exact + z*h_cand ----
#pragma unroll
    for (int q = 0; q < 8; ++q) {
        int ns = q & 3, ms = q >> 2;
        int c0 = ncol0 + ns * 8 + 2 * t;
        float bh0 = __ldg(&g_bias[2 * D + c0]), bh1 = __ldg(&g_bias[2 * D + c0 + 1]);
        long long gr1 = row0 + mrow0 + ms * 16 + g, gr2 = gr1 + 8;
        float2 hA = *(const float2*)(h + gr1 * D + c0);   // exact h from gmem
        float2 hB = *(const float2*)(h + gr2 * D + c0);
        float hc0 = tanhf(acc[q][0] + bh0);
        float hc1 = tanhf(acc[q][1] + bh1);
        float hc2 = tanhf(acc[q][2] + bh0);
        float hc3 = tanhf(acc[q][3] + bh1);
        __half2 p01 = *(__half2*)&zpk[q * 2];
        __half2 p23 = *(__half2*)&zpk[q * 2 + 1];
        float z0 = __low2float(p01), z1 = __high2float(p01);
        float z2 = __low2float(p23), z3 = __high2float(p23);
        float ht0 = (1.f - z0) * hA.x + z0 * hc0;
        float ht1 = (1.f - z1) * hA.y + z1 * hc1;
        float ht2 = (1.f - z2) * hB.x + z2 * hc2;
        float ht3 = (1.f - z3) * hB.y + z3 * hc3;
        *(float2*)(out + gr1 * D + c0)            = make_float2(ht0, ht1);
        *(float2*)(out + gr2 * D + c0)            = make_float2(ht2, ht3);
        *(float2*)(out + half_off + gr1 * D + c0) = make_float2(hc0, hc1);
        *(float2*)(out + half_off + gr2 * D + c0) = make_float2(hc2, hc3);
    }
}

// ---------------------------------------------------------------------------
// launch: exactly 2 kernels per call
// ---------------------------------------------------------------------------
extern "C" void kernel_launch(void* const* d_in, const int* in_sizes, int n_in,
                              void* d_out, int out_size) {
    const float* x  = (const float*)d_in[0];
    const float* h  = (const float*)d_in[1];
    const float* Wz = (const float*)d_in[2];
    const float* Uz = (const float*)d_in[3];
    const float* Bz = (const float*)d_in[4];
    const float* Wr = (const float*)d_in[5];
    const float* Ur = (const float*)d_in[6];
    const float* Br = (const float*)d_in[7];
    const float* Wh = (const float*)d_in[8];
    const float* Uh = (const float*)d_in[9];
    const float* Bh = (const float*)d_in[10];

    const int rows = in_sizes[0] / D;      // 262144
    const int grid = rows / 64;            // 4096

    cudaFuncSetAttribute(gru_kernel, cudaFuncAttributeMaxDynamicSharedMemorySize, SMEM_BYTES);

    prep_kernel<<<323, NT>>>(Wz, Uz, Wr, Ur, Wh, Uh, Bz, Br, Bh);

    long long half_off = (long long)out_size / 2;   // h_t first, h_cand second
    gru_kernel<<<grid, NT, SMEM_BYTES>>>(x, h, (float*)d_out, half_off);
}

// round 16
// speedup vs baseline: 2.0722x; 2.0722x over previous
#include <cuda_runtime.h>
#include <cuda_fp16.h>
#include <stdint.h>

#define D  128
#define NT 512

// SMEM uint32 offsets (fp16 pairs packed in uint32)
#define XS 0            // x tile [64 rows][64 pk]  (16KB)
#define HS 4096         // h tile; later r*h        (16KB)
#define PB 8192         // 3 x quarter-panel buffers (3 x 8KB)
#define SMEM_BYTES ((8192 + 3 * 2048) * 4)   // 57,344 B

// ---------------------------------------------------------------------------
// device globals: biases + prepped fp16 weight panel images
// ---------------------------------------------------------------------------
__device__ float g_bias[3 * D];
__device__ __align__(256) uint32_t g_wph[20 * 2048];  // 20 panels x [128n][16pk]

__device__ __forceinline__ float sigmoidf_(float v) { return 1.0f / (1.0f + expf(-v)); }

__device__ __forceinline__ uint32_t smem_u32(const void* p) {
    uint32_t a;
    asm("{ .reg .u64 t; cvta.to.shared.u64 t, %1; cvt.u32.u64 %0, t; }" : "=r"(a) : "l"(p));
    return a;
}
__device__ __forceinline__ void cp16(uint32_t saddr, const void* gaddr) {
    asm volatile("cp.async.cg.shared.global [%0], [%1], 16;" :: "r"(saddr), "l"(gaddr));
}
#define CP_COMMIT() asm volatile("cp.async.commit_group;" ::: "memory")
#define CP_WAIT1()  asm volatile("cp.async.wait_group 1;" ::: "memory")
#define CP_WAIT0()  asm volatile("cp.async.wait_group 0;" ::: "memory")

__device__ __forceinline__ uint32_t packh2(float a, float b) {
    __half2 p = __floats2half2_rn(a, b);
    return *(uint32_t*)&p;
}

// ---------------------------------------------------------------------------
// prep: bake fp16 panels (blocks 0..79) + bias column sums (blocks 80..82)
// panel p = G*4 + q (G: Wz,Uz,Wr+Ur,Wh,Uh). Packed pair pk (k = q*32 + 2pk)
// stored at p*2048 + n*16 + (pk ^ (((n>>1)&3)<<2)).  G0..2 transposed.
// ---------------------------------------------------------------------------
__global__ void prep_kernel(const float* __restrict__ Wz, const float* __restrict__ Uz,
                            const float* __restrict__ Wr, const float* __restrict__ Ur,
                            const float* __restrict__ Wh, const float* __restrict__ Uh,
                            const float* __restrict__ Bz, const float* __restrict__ Br,
                            const float* __restrict__ Bh) {
    if (blockIdx.x >= 80) {                  // bias: one block per matrix
        int m = blockIdx.x - 80;
        int j = threadIdx.x;
        if (j < D) {
            const float* B = (m == 0) ? Bz : (m == 1) ? Br : Bh;
            float s = 0.f;
            for (int i = 0; i < D; ++i) s += B[i * D + j];
            g_bias[m * D + j] = s;
        }
        return;
    }
    int idx = blockIdx.x * blockDim.x + threadIdx.x;   // 40960 packed entries
    int p   = idx >> 11;
    int rem = idx & 2047;
    int n   = rem >> 4;
    int spk = rem & 15;
    int pk  = spk ^ (((n >> 1) & 3) << 2);   // invert swizzle -> source pk
    int G = p >> 2, q = p & 3;
    int k0 = q * 32 + pk * 2, k1 = k0 + 1;
    float v0, v1;
    if      (G == 0) { v0 = Wz[k0 * D + n];                    v1 = Wz[k1 * D + n]; }
    else if (G == 1) { v0 = Uz[k0 * D + n];                    v1 = Uz[k1 * D + n]; }
    else if (G == 2) { v0 = Wr[k0 * D + n] + Ur[k0 * D + n];   v1 = Wr[k1 * D + n] + Ur[k1 * D + n]; }
    else if (G == 3) { v0 = Wh[n * D + k0];                    v1 = Wh[n * D + k1]; }
    else             { v0 = Uh[n * D + k0];                    v1 = Uh[n * D + k1]; }
    g_wph[idx] = packh2(v0, v1);
}

// ---------------------------------------------------------------------------
// fp16 mma m16n8k16, fp32 accumulate
// ---------------------------------------------------------------------------
__device__ __forceinline__ void mma16(float* d, const uint32_t* a, uint32_t b0, uint32_t b1) {
    asm volatile(
        "mma.sync.aligned.m16n8k16.row.col.f32.f16.f16.f32 "
        "{%0,%1,%2,%3}, {%4,%5,%6,%7}, {%8,%9}, {%0,%1,%2,%3};"
        : "+f"(d[0]), "+f"(d[1]), "+f"(d[2]), "+f"(d[3])
        : "r"(a[0]), "r"(a[1]), "r"(a[2]), "r"(a[3]), "r"(b0), "r"(b1));
}

// one K-quarter slab: warp tile 16M x 32N x 32K = 2 k16-steps
// tile: [64r][64pk], pos = r*64 + (pk ^ ((r&7)<<2)); panel: [128n][16pk],
// pos = n*16 + (pk ^ (((n>>1)&3)<<2)).  All accesses bank-conflict-free.
__device__ __forceinline__ void mma_q(const uint32_t* __restrict__ As, int qoff,
                                      const uint32_t* __restrict__ Ws,
                                      float acc[4][4],
                                      int mrow0, int ncol0, int g, int t) {
    const uint32_t* a0p = As + (mrow0 + g) * 64;
    const uint32_t* a1p = a0p + 8 * 64;
    const int asw = g << 2;
    const int bsw = ((g >> 1) & 3) << 2;
#pragma unroll
    for (int s = 0; s < 2; ++s) {
        int ao1 = (qoff + s * 8 + t) ^ asw;
        int ao2 = ao1 ^ 4;
        uint32_t A[4];
        A[0] = a0p[ao1]; A[1] = a1p[ao1];   // a0: row g k-lo, a1: row g+8 k-lo
        A[2] = a0p[ao2]; A[3] = a1p[ao2];   // a2/a3: k-hi
        int bo1 = (s * 8 + t) ^ bsw;
        int bo2 = bo1 ^ 4;
#pragma unroll
        for (int ns = 0; ns < 4; ++ns) {
            const uint32_t* bp = Ws + (ncol0 + ns * 8 + g) * 16;
            mma16(acc[ns], A, bp[bo1], bp[bo2]);
        }
    }
}

// ---------------------------------------------------------------------------
// fused GRU: 64 rows/CTA, 512 threads (16 warps of 16x32), 2 CTAs/SM
// all-fp16 operands; single live acc; z and h parked as fp16 pairs
// ---------------------------------------------------------------------------
__global__ __launch_bounds__(NT, 2)
void gru_kernel(const float* __restrict__ x, const float* __restrict__ h,
                float* __restrict__ out, long long half_off) {
    extern __shared__ uint32_t smu[];
    const int tid   = threadIdx.x;
    const int lane  = tid & 31;
    const int warp  = tid >> 5;
    const int g     = lane >> 2;
    const int t     = lane & 3;
    const int mrow0 = (warp >> 2) * 16;    // 0,16,32,48
    const int ncol0 = (warp & 3) * 32;     // 0,32,64,96
    const long long row0 = (long long)blockIdx.x * 64;

    const uint32_t pbs = smem_u32(smu + PB) + (uint32_t)tid * 16;

    // ---- kick off panel pipeline: img0 -> buf0, img1 -> buf1 ----
    cp16(pbs,        (const char*)g_wph + tid * 16);
    CP_COMMIT();
    cp16(pbs + 8192, (const char*)(g_wph + 2048) + tid * 16);
    CP_COMMIT();

    // ---- stage x, h as fp16 pairs into swizzled tiles (overlaps cp.async) ----
#pragma unroll
    for (int i = 0; i < 4; ++i) {
        int idx = tid + i * NT;                  // 0..2047
        int r = idx >> 5, pc = (idx & 31) * 2;   // pair-column, even
        int pos = r * 64 + (pc ^ ((r & 7) << 2));
        float4 vx = *(const float4*)(x + (row0 + r) * D + pc * 2);
        uint2 sx; sx.x = packh2(vx.x, vx.y); sx.y = packh2(vx.z, vx.w);
        *(uint2*)(smu + XS + pos) = sx;
        float4 vh = *(const float4*)(h + (row0 + r) * D + pc * 2);
        uint2 sh; sh.x = packh2(vh.x, vh.y); sh.y = packh2(vh.z, vh.w);
        *(uint2*)(smu + HS + pos) = sh;
    }
    CP_WAIT1();
    __syncthreads();

    float acc[4][4];
#pragma unroll
    for (int ns = 0; ns < 4; ++ns)
#pragma unroll
        for (int j = 0; j < 4; ++j) acc[ns][j] = 0.f;

    // slab p: issue img p+2 -> buf (p+2)%3; mma img p; wait img p+1; sync
#define QITER(p, ABASE) do {                                                     \
        if ((p) + 2 <= 19) {                                                     \
            cp16(pbs + (uint32_t)((((p) + 2) % 3) * 8192),                       \
                 (const char*)(g_wph + ((p) + 2) * 2048) + tid * 16);            \
            CP_COMMIT();                                                         \
        }                                                                        \
        mma_q(smu + (ABASE), ((p) & 3) * 16, smu + PB + (((p) % 3) * 2048),      \
              acc, mrow0, ncol0, g, t);                                          \
        if ((p) + 2 <= 19) { CP_WAIT1(); } else { CP_WAIT0(); }                  \
        __syncthreads();                                                         \
    } while (0)

    // ---- phase 1: z_pre = x@Wz + h@Uz ----
    QITER(0, XS); QITER(1, XS); QITER(2, XS); QITER(3, XS);
    QITER(4, HS); QITER(5, HS); QITER(6, HS); QITER(7, HS);

    // E1a: z = sigmoid(z_pre + bz) -> fp16 pairs; reset acc
    uint32_t zpk[8];
#pragma unroll
    for (int ns = 0; ns < 4; ++ns) {
        int c0 = ncol0 + ns * 8 + 2 * t;
        float bz0 = __ldg(&g_bias[c0]), bz1 = __ldg(&g_bias[c0 + 1]);
        zpk[ns * 2]     = packh2(sigmoidf_(acc[ns][0] + bz0), sigmoidf_(acc[ns][1] + bz1));
        zpk[ns * 2 + 1] = packh2(sigmoidf_(acc[ns][2] + bz0), sigmoidf_(acc[ns][3] + bz1));
        acc[ns][0] = 0.f; acc[ns][1] = 0.f; acc[ns][2] = 0.f; acc[ns][3] = 0.f;
    }

    // ---- phase 2: r_pre = x@(Wr+Ur) ----
    QITER(8, XS); QITER(9, XS); QITER(10, XS); QITER(11, XS);

    // E1b: r = sigmoid(r_pre+br); HS <- fp16(r*h); park h (fp16) in hpk; reset acc
    uint32_t hpk[8];
#pragma unroll
    for (int ns = 0; ns < 4; ++ns) {
        int c0 = ncol0 + ns * 8 + 2 * t;
        float br0 = __ldg(&g_bias[D + c0]), br1 = __ldg(&g_bias[D + c0 + 1]);
        int r1 = mrow0 + g;
        int pk = (c0 >> 1) ^ (g << 2);
        int pos1 = r1 * 64 + pk, pos2 = (r1 + 8) * 64 + pk;
        uint32_t hw1 = smu[HS + pos1], hw2 = smu[HS + pos2];
        hpk[ns * 2] = hw1; hpk[ns * 2 + 1] = hw2;
        float2 hA = __half22float2(*(__half2*)&hw1);
        float2 hB = __half22float2(*(__half2*)&hw2);
        float q0 = sigmoidf_(acc[ns][0] + br0);
        float q1 = sigmoidf_(acc[ns][1] + br1);
        float q2 = sigmoidf_(acc[ns][2] + br0);
        float q3 = sigmoidf_(acc[ns][3] + br1);
        smu[HS + pos1] = packh2(q0 * hA.x, q1 * hA.y);
        smu[HS + pos2] = packh2(q2 * hB.x, q3 * hB.y);
        acc[ns][0] = 0.f; acc[ns][1] = 0.f; acc[ns][2] = 0.f; acc[ns][3] = 0.f;
    }
    // slabs 12-15 read XS only; per-slab syncs order E1b's HS writes before slab 16

    // ---- phase 3: hc_pre = x@Wh^T + rh@Uh^T ----
    QITER(12, XS); QITER(13, XS); QITER(14, XS); QITER(15, XS);
    QITER(16, HS); QITER(17, HS); QITER(18, HS); QITER(19, HS);
#undef QITER

    // ---- E2: h_cand = tanh(hc_pre+bh); h_t = (1-z)*h + z*h_cand ----
#pragma unroll
    for (int ns = 0; ns < 4; ++ns) {
        int c0 = ncol0 + ns * 8 + 2 * t;
        float bh0 = __ldg(&g_bias[2 * D + c0]), bh1 = __ldg(&g_bias[2 * D + c0 + 1]);
        long long gr1 = row0 + mrow0 + g, gr2 = gr1 + 8;
        float2 hA = __half22float2(*(__half2*)&hpk[ns * 2]);
        float2 hB = __half22float2(*(__half2*)&hpk[ns * 2 + 1]);
        float2 zA = __half22float2(*(__half2*)&zpk[ns * 2]);
        float2 zB = __half22float2(*(__half2*)&zpk[ns * 2 + 1]);
        float hc0 = tanhf(acc[ns][0] + bh0);
        float hc1 = tanhf(acc[ns][1] + bh1);
        float hc2 = tanhf(acc[ns][2] + bh0);
        float hc3 = tanhf(acc[ns][3] + bh1);
        float ht0 = (1.f - zA.x) * hA.x + zA.x * hc0;
        float ht1 = (1.f - zA.y) * hA.y + zA.y * hc1;
        float ht2 = (1.f - zB.x) * hB.x + zB.x * hc2;
        float ht3 = (1.f - zB.y) * hB.y + zB.y * hc3;
        *(float2*)(out + gr1 * D + c0)            = make_float2(ht0, ht1);
        *(float2*)(out + gr2 * D + c0)            = make_float2(ht2, ht3);
        *(float2*)(out + half_off + gr1 * D + c0) = make_float2(hc0, hc1);
        *(float2*)(out + half_off + gr2 * D + c0) = make_float2(hc2, hc3);
    }
}

// ---------------------------------------------------------------------------
// launch: exactly 2 kernels per call
// ---------------------------------------------------------------------------
extern "C" void kernel_launch(void* const* d_in, const int* in_sizes, int n_in,
                              void* d_out, int out_size) {
    const float* x  = (const float*)d_in[0];
    const float* h  = (const float*)d_in[1];
    const float* Wz = (const float*)d_in[2];
    const float* Uz = (const float*)d_in[3];
    const float* Bz = (const float*)d_in[4];
    const float* Wr = (const float*)d_in[5];
    const float* Ur = (const float*)d_in[6];
    const float* Br = (const float*)d_in[7];
    const float* Wh = (const float*)d_in[8];
    const float* Uh = (const float*)d_in[9];
    const float* Bh = (const float*)d_in[10];

    const int rows = in_sizes[0] / D;      // 262144
    const int grid = rows / 64;            // 4096

    cudaFuncSetAttribute(gru_kernel, cudaFuncAttributeMaxDynamicSharedMemorySize, SMEM_BYTES);

    prep_kernel<<<83, NT>>>(Wz, Uz, Wr, Ur, Wh, Uh, Bz, Br, Bh);

    long long half_off = (long long)out_size / 2;   // h_t first, h_cand second
    gru_kernel<<<grid, NT, SMEM_BYTES>>>(x, h, (float*)d_out, half_off);
}